// round 4
// baseline (speedup 1.0000x reference)
#include <cuda_runtime.h>
#include <cuda_bf16.h>
#include <cstdint>

#define BB 2
#define SS 2048
#define DD 4096
#define NH 32
#define NKVH 8
#define HD 128
#define SWIN 4096
#define KVREP 4
#define ATT_SCALE 0.08838834764831845f
#define NEGBIG -1000000000.0f
#define MTOT (BB * SS)

// ---------------- scratch (device globals) ----------------
__device__ float g_xq[(size_t)MTOT * NH * HD];
__device__ float g_xk[(size_t)MTOT * NKVH * HD];
__device__ float g_xv[(size_t)MTOT * NKVH * HD];
__device__ __nv_bfloat16 g_xh[(size_t)MTOT * DD];
__device__ __nv_bfloat16 g_xl[(size_t)MTOT * DD];
__device__ __nv_bfloat16 g_wqh[(size_t)DD * DD];
__device__ __nv_bfloat16 g_wql[(size_t)DD * DD];
__device__ __nv_bfloat16 g_wkh[(size_t)DD * NKVH * HD];
__device__ __nv_bfloat16 g_wkl[(size_t)DD * NKVH * HD];
__device__ __nv_bfloat16 g_wvh[(size_t)DD * NKVH * HD];
__device__ __nv_bfloat16 g_wvl[(size_t)DD * NKVH * HD];
__device__ __nv_bfloat16 g_woh[(size_t)DD * DD];
__device__ __nv_bfloat16 g_wol[(size_t)DD * DD];
__device__ __nv_bfloat16 g_ah[(size_t)MTOT * DD];
__device__ __nv_bfloat16 g_al[(size_t)MTOT * DD];

// ---------------- helpers ----------------
__device__ __forceinline__ void cpa16(uint32_t s, const void* g) {
    asm volatile("cp.async.cg.shared.global [%0], [%1], 16;" :: "r"(s), "l"(g));
}

// ---------------- pre-pass: fp32 -> bf16 hi/lo (same layout) ----------------
__global__ void split_kernel(const float4* __restrict__ in,
                             __nv_bfloat16* __restrict__ hi,
                             __nv_bfloat16* __restrict__ lo, int n4) {
    int i = blockIdx.x * blockDim.x + threadIdx.x;
    if (i >= n4) return;
    float4 v = in[i];
    __nv_bfloat16 h0 = __float2bfloat16(v.x), h1 = __float2bfloat16(v.y);
    __nv_bfloat16 h2 = __float2bfloat16(v.z), h3 = __float2bfloat16(v.w);
    __nv_bfloat16 l0 = __float2bfloat16(v.x - __bfloat162float(h0));
    __nv_bfloat16 l1 = __float2bfloat16(v.y - __bfloat162float(h1));
    __nv_bfloat16 l2 = __float2bfloat16(v.z - __bfloat162float(h2));
    __nv_bfloat16 l3 = __float2bfloat16(v.w - __bfloat162float(h3));
    __nv_bfloat162* hp = (__nv_bfloat162*)(hi + (size_t)i * 4);
    __nv_bfloat162* lp = (__nv_bfloat162*)(lo + (size_t)i * 4);
    hp[0] = __halves2bfloat162(h0, h1);
    hp[1] = __halves2bfloat162(h2, h3);
    lp[0] = __halves2bfloat162(l0, l1);
    lp[1] = __halves2bfloat162(l2, l3);
}

// ---------------- pre-pass: W[K,N] fp32 -> Wt[N,K] bf16 hi/lo ----------------
__global__ void tsplit_kernel(const float* __restrict__ W,
                              __nv_bfloat16* __restrict__ Th,
                              __nv_bfloat16* __restrict__ Tl, int K, int N) {
    __shared__ float tile[32][33];
    const int tx = threadIdx.x, ty = threadIdx.y;
    const int nb = blockIdx.x * 32, kb = blockIdx.y * 32;
#pragma unroll
    for (int i = 0; i < 32; i += 8)
        tile[ty + i][tx] = W[(size_t)(kb + ty + i) * N + nb + tx];
    __syncthreads();
#pragma unroll
    for (int i = 0; i < 32; i += 8) {
        float v = tile[tx][ty + i];
        __nv_bfloat16 h = __float2bfloat16(v);
        __nv_bfloat16 l = __float2bfloat16(v - __bfloat162float(h));
        size_t o = (size_t)(nb + ty + i) * K + kb + tx;
        Th[o] = h;
        Tl[o] = l;
    }
}

// ---------------- bf16x3 HMMA GEMM ----------------
// C[M,N](fp32) = (Ah+Al)[M,K] @ (Bh+Bl)^T, B* stored [N,K] row-major.
#define GM 128
#define GN 128
#define GK 32
#define APAD 40                          // row stride in bf16 elements (80 B)
#define REGE (128 * APAD)                // elements per region
#define STAGEE (4 * REGE)                // Ah, Al, Bh, Bl
#define GSMEM (2 * STAGEE * 2)           // bytes (2 stages)

__device__ __forceinline__ void hmma(float* c, const uint32_t* a, const uint32_t* b) {
    asm volatile(
        "mma.sync.aligned.m16n8k16.row.col.f32.bf16.bf16.f32 "
        "{%0,%1,%2,%3}, {%4,%5,%6,%7}, {%8,%9}, {%0,%1,%2,%3};"
        : "+f"(c[0]), "+f"(c[1]), "+f"(c[2]), "+f"(c[3])
        : "r"(a[0]), "r"(a[1]), "r"(a[2]), "r"(a[3]), "r"(b[0]), "r"(b[1]));
}

__global__ __launch_bounds__(256, 2) void hgemm3(
    const __nv_bfloat16* __restrict__ Ah, const __nv_bfloat16* __restrict__ Al,
    const __nv_bfloat16* __restrict__ Bh, const __nv_bfloat16* __restrict__ Bl,
    float* __restrict__ C, int M, int N, int K)
{
    extern __shared__ __align__(16) __nv_bfloat16 sm[];
    const uint32_t sb = (uint32_t)__cvta_generic_to_shared(sm);
    const int tid = threadIdx.x;
    const int lane = tid & 31;
    const int wid = tid >> 5;
    const int g = lane >> 2;
    const int tg = lane & 3;
    const int wm = (wid >> 2) * 64;
    const int wn = (wid & 3) * 32;
    const int row0 = blockIdx.y * GM;
    const int col0 = blockIdx.x * GN;

    // loader mapping: region = Ah/Al/Bh/Bl, 64 threads each, 8 chunks of 16B
    const int lreg = tid >> 6;
    const int lu = tid & 63;
    const __nv_bfloat16* base = (lreg == 0) ? Ah : (lreg == 1) ? Al : (lreg == 2) ? Bh : Bl;
    const int r0 = (lreg < 2) ? row0 : col0;

    float acc[4][4][4];
#pragma unroll
    for (int i = 0; i < 4; i++)
#pragma unroll
        for (int j = 0; j < 4; j++)
#pragma unroll
            for (int r = 0; r < 4; r++) acc[i][j][r] = 0.0f;

#define LOADSTAGE(s, k0)                                                          \
    do {                                                                          \
        const uint32_t d0 = sb + ((s) * STAGEE + lreg * REGE) * 2;                \
        _Pragma("unroll")                                                         \
        for (int it = 0; it < 8; it++) {                                          \
            int chunk = it * 64 + lu;                                             \
            int row = chunk >> 2;                                                 \
            int cc = chunk & 3;                                                   \
            cpa16(d0 + (uint32_t)(row * APAD + cc * 8) * 2,                       \
                  base + (size_t)(r0 + row) * K + (k0) + cc * 8);                 \
        }                                                                         \
        asm volatile("cp.async.commit_group;");                                   \
    } while (0)

    const int T = K / GK;
    LOADSTAGE(0, 0);

    for (int t = 0; t < T; t++) {
        __syncthreads();
        if (t + 1 < T) {
            LOADSTAGE((t + 1) & 1, (t + 1) * GK);
            asm volatile("cp.async.wait_group 1;");
        } else {
            asm volatile("cp.async.wait_group 0;");
        }
        __syncthreads();

        const int s = t & 1;
        const __nv_bfloat16* sAh = sm + s * STAGEE;
        const __nv_bfloat16* sAl = sAh + REGE;
        const __nv_bfloat16* sBh = sAl + REGE;
        const __nv_bfloat16* sBl = sBh + REGE;

#pragma unroll
        for (int ks = 0; ks < GK; ks += 16) {
            uint32_t bh[4][2], bl[4][2];
#pragma unroll
            for (int nt = 0; nt < 4; nt++) {
                int rb = (wn + nt * 8 + g) * APAD + ks + 2 * tg;
                bh[nt][0] = *(const uint32_t*)(sBh + rb);
                bh[nt][1] = *(const uint32_t*)(sBh + rb + 8);
                bl[nt][0] = *(const uint32_t*)(sBl + rb);
                bl[nt][1] = *(const uint32_t*)(sBl + rb + 8);
            }
#pragma unroll
            for (int mt = 0; mt < 4; mt++) {
                int ra = (wm + mt * 16 + g) * APAD + ks + 2 * tg;
                uint32_t ah[4], al[4];
                ah[0] = *(const uint32_t*)(sAh + ra);
                ah[1] = *(const uint32_t*)(sAh + ra + 8 * APAD);
                ah[2] = *(const uint32_t*)(sAh + ra + 8);
                ah[3] = *(const uint32_t*)(sAh + ra + 8 * APAD + 8);
                al[0] = *(const uint32_t*)(sAl + ra);
                al[1] = *(const uint32_t*)(sAl + ra + 8 * APAD);
                al[2] = *(const uint32_t*)(sAl + ra + 8);
                al[3] = *(const uint32_t*)(sAl + ra + 8 * APAD + 8);
#pragma unroll
                for (int nt = 0; nt < 4; nt++) {
                    hmma(acc[mt][nt], ah, bh[nt]);
                    hmma(acc[mt][nt], ah, bl[nt]);
                    hmma(acc[mt][nt], al, bh[nt]);
                }
            }
        }
    }

#pragma unroll
    for (int mt = 0; mt < 4; mt++) {
#pragma unroll
        for (int nt = 0; nt < 4; nt++) {
            int r = row0 + wm + mt * 16 + g;
            int c = col0 + wn + nt * 8 + tg * 2;
            *(float2*)&C[(size_t)r * N + c] = make_float2(acc[mt][nt][0], acc[mt][nt][1]);
            *(float2*)&C[(size_t)(r + 8) * N + c] = make_float2(acc[mt][nt][2], acc[mt][nt][3]);
        }
    }
#undef LOADSTAGE
}

// ---------------- RoPE (interleaved pairs), in place ----------------
__global__ void rope_kernel(float* __restrict__ data,
                            const float* __restrict__ cosf,
                            const float* __restrict__ sinf,
                            int nheads)
{
    size_t idx = (size_t)blockIdx.x * blockDim.x + threadIdx.x;
    size_t total = (size_t)BB * SS * nheads * (HD / 2);
    if (idx >= total) return;
    int i = (int)(idx % (HD / 2));
    size_t rem = idx / (HD / 2);
    int hh = (int)(rem % nheads);
    size_t bs = rem / nheads;
    int s = (int)(bs % SS);
    float c = cosf[(size_t)s * (HD / 2) + i];
    float sn = sinf[(size_t)s * (HD / 2) + i];
    float* p = data + (bs * nheads + hh) * HD + 2 * i;
    float x1 = p[0], x2 = p[1];
    p[0] = x1 * c - x2 * sn;
    p[1] = x1 * sn + x2 * c;
}

// ---------------- cache fill ----------------
__global__ void cache_kernel(const float* __restrict__ xk, const float* __restrict__ xv,
                             float* __restrict__ ck, float* __restrict__ cv)
{
    size_t idx = (size_t)blockIdx.x * blockDim.x + threadIdx.x;
    size_t total = (size_t)BB * SWIN * NKVH * HD;
    if (idx >= total) return;
    int d = (int)(idx % HD);
    size_t r = idx / HD;
    int kvh = (int)(r % NKVH); r /= NKVH;
    int s = (int)(r % SWIN);
    int b = (int)(r / SWIN);
    float kval = 0.0f, vval = 0.0f;
    if (s < SS) {
        size_t src = (((size_t)b * SS + s) * NKVH + kvh) * HD + d;
        kval = xk[src];
        vval = xv[src];
    }
    ck[idx] = kval;
    cv[idx] = vval;
}

// ---------------- flash-style causal attention ----------------
#define BQ 64
#define BKEY 32

__global__ __launch_bounds__(BQ) void flash_kernel(
    const float* __restrict__ xq, const float* __restrict__ xk,
    const float* __restrict__ xv,
    __nv_bfloat16* __restrict__ outh, __nv_bfloat16* __restrict__ outl)
{
    const int qt = blockIdx.x;
    const int h = blockIdx.y;
    const int b = blockIdx.z;
    const int tid = threadIdx.x;
    const int q = qt * BQ + tid;
    const int kvh = h / KVREP;

    __shared__ float Qs[BQ][HD + 4];
    __shared__ float Ssc[BQ][BKEY + 1];

    const float* qbase = xq + (((size_t)b * SS + (size_t)qt * BQ) * NH + h) * HD;
    for (int j = tid; j < BQ * (HD / 4); j += BQ) {
        int row = j / (HD / 4);
        int c = j % (HD / 4);
        float4 v = *(const float4*)(qbase + (size_t)row * NH * HD + c * 4);
        *(float4*)&Qs[row][c * 4] = v;
    }
    __syncthreads();

    float o[HD];
#pragma unroll
    for (int d = 0; d < HD; d++) o[d] = 0.0f;
    float m = -1e30f, l = 0.0f;

    const int ntiles = q / BKEY + 1;
    for (int kt = 0; kt < ntiles; kt++) {
        const float* kbase = xk + (((size_t)b * SS + (size_t)kt * BKEY) * NKVH + kvh) * HD;
        float tmax = -1e30f;
        for (int k = 0; k < BKEY; k++) {
            const int kg = kt * BKEY + k;
            const float* kp = kbase + (size_t)k * NKVH * HD;
            float sk = 0.0f;
#pragma unroll
            for (int d = 0; d < HD; d += 4) {
                float4 kv = *(const float4*)(kp + d);
                float4 qv = *(const float4*)&Qs[tid][d];
                sk += qv.x * kv.x + qv.y * kv.y + qv.z * kv.z + qv.w * kv.w;
            }
            sk *= ATT_SCALE;
            if (kg > q) sk += NEGBIG;
            Ssc[tid][k] = sk;
            tmax = fmaxf(tmax, sk);
        }
        float mnew = fmaxf(m, tmax);
        float corr = __expf(m - mnew);
#pragma unroll
        for (int d = 0; d < HD; d++) o[d] *= corr;
        l *= corr;

        const float* vbase = xv + (((size_t)b * SS + (size_t)kt * BKEY) * NKVH + kvh) * HD;
        for (int k = 0; k < BKEY; k++) {
            float p = __expf(Ssc[tid][k] - mnew);
            l += p;
            const float* vp = vbase + (size_t)k * NKVH * HD;
#pragma unroll
            for (int d = 0; d < HD; d += 4) {
                float4 vv = *(const float4*)(vp + d);
                o[d + 0] += p * vv.x;
                o[d + 1] += p * vv.y;
                o[d + 2] += p * vv.z;
                o[d + 3] += p * vv.w;
            }
        }
        m = mnew;
    }

    const float inv = 1.0f / l;
    size_t obase = (((size_t)b * SS + q) * NH + h) * HD;
#pragma unroll
    for (int d = 0; d < HD; d += 2) {
        float r0 = o[d] * inv, r1 = o[d + 1] * inv;
        __nv_bfloat16 h0 = __float2bfloat16(r0), h1 = __float2bfloat16(r1);
        __nv_bfloat16 l0 = __float2bfloat16(r0 - __bfloat162float(h0));
        __nv_bfloat16 l1 = __float2bfloat16(r1 - __bfloat162float(h1));
        *(__nv_bfloat162*)(outh + obase + d) = __halves2bfloat162(h0, h1);
        *(__nv_bfloat162*)(outl + obase + d) = __halves2bfloat162(l0, l1);
    }
}

// ---------------- launch ----------------
extern "C" void kernel_launch(void* const* d_in, const int* in_sizes, int n_in,
                              void* d_out, int out_size)
{
    const float* x    = (const float*)d_in[0];
    const float* cosf = (const float*)d_in[1];
    const float* sinf = (const float*)d_in[2];
    const float* wq = (const float*)d_in[7];
    const float* wk = (const float*)d_in[8];
    const float* wv = (const float*)d_in[9];
    const float* wo = (const float*)d_in[10];

    float* out = (float*)d_out;
    float* ck = out + (size_t)MTOT * DD;
    float* cv = ck + (size_t)BB * SWIN * NKVH * HD;

    float *xq, *xk, *xv;
    __nv_bfloat16 *xh, *xl, *wqh, *wql, *wkh, *wkl, *wvh, *wvl, *woh, *wol, *ah, *al;
    cudaGetSymbolAddress((void**)&xq, g_xq);
    cudaGetSymbolAddress((void**)&xk, g_xk);
    cudaGetSymbolAddress((void**)&xv, g_xv);
    cudaGetSymbolAddress((void**)&xh, g_xh);
    cudaGetSymbolAddress((void**)&xl, g_xl);
    cudaGetSymbolAddress((void**)&wqh, g_wqh);
    cudaGetSymbolAddress((void**)&wql, g_wql);
    cudaGetSymbolAddress((void**)&wkh, g_wkh);
    cudaGetSymbolAddress((void**)&wkl, g_wkl);
    cudaGetSymbolAddress((void**)&wvh, g_wvh);
    cudaGetSymbolAddress((void**)&wvl, g_wvl);
    cudaGetSymbolAddress((void**)&woh, g_woh);
    cudaGetSymbolAddress((void**)&wol, g_wol);
    cudaGetSymbolAddress((void**)&ah, g_ah);
    cudaGetSymbolAddress((void**)&al, g_al);

    cudaFuncSetAttribute(hgemm3, cudaFuncAttributeMaxDynamicSharedMemorySize, GSMEM);

    // pre-pass: split x; transpose+split weights
    {
        int n4 = (int)((size_t)MTOT * DD / 4);
        split_kernel<<<(n4 + 255) / 256, 256>>>((const float4*)x, xh, xl, n4);
        dim3 blk(32, 8);
        tsplit_kernel<<<dim3(DD / 32, DD / 32), blk>>>(wq, wqh, wql, DD, DD);
        tsplit_kernel<<<dim3((NKVH * HD) / 32, DD / 32), blk>>>(wk, wkh, wkl, DD, NKVH * HD);
        tsplit_kernel<<<dim3((NKVH * HD) / 32, DD / 32), blk>>>(wv, wvh, wvl, DD, NKVH * HD);
        tsplit_kernel<<<dim3(DD / 32, DD / 32), blk>>>(wo, woh, wol, NH * HD, DD);
    }

    // QKV projections
    hgemm3<<<dim3(DD / GN, MTOT / GM), 256, GSMEM>>>(xh, xl, wqh, wql, xq, MTOT, DD, DD);
    hgemm3<<<dim3((NKVH * HD) / GN, MTOT / GM), 256, GSMEM>>>(xh, xl, wkh, wkl, xk, MTOT, NKVH * HD, DD);
    hgemm3<<<dim3((NKVH * HD) / GN, MTOT / GM), 256, GSMEM>>>(xh, xl, wvh, wvl, xv, MTOT, NKVH * HD, DD);

    // RoPE
    {
        size_t tq = (size_t)BB * SS * NH * (HD / 2);
        rope_kernel<<<(unsigned)((tq + 255) / 256), 256>>>(xq, cosf, sinf, NH);
        size_t tk = (size_t)BB * SS * NKVH * (HD / 2);
        rope_kernel<<<(unsigned)((tk + 255) / 256), 256>>>(xk, cosf, sinf, NKVH);
    }

    // cache outputs
    {
        size_t tc = (size_t)BB * SWIN * NKVH * HD;
        cache_kernel<<<(unsigned)((tc + 255) / 256), 256>>>(xk, xv, ck, cv);
    }

    // attention (emits bf16 hi/lo for the wo GEMM)
    {
        dim3 gf(SS / BQ, NH, BB);
        flash_kernel<<<gf, BQ>>>(xq, xk, xv, ah, al);
    }

    // output projection
    hgemm3<<<dim3(DD / GN, MTOT / GM), 256, GSMEM>>>(ah, al, woh, wol, out, MTOT, DD, NH * HD);
}

// round 5
// speedup vs baseline: 2.1084x; 2.1084x over previous
#include <cuda_runtime.h>
#include <cuda_bf16.h>
#include <cstdint>

#define BB 2
#define SS 2048
#define DD 4096
#define NH 32
#define NKVH 8
#define HD 128
#define SWIN 4096
#define KVREP 4
#define ATT_SCALE 0.08838834764831845f
#define NEGBIG -1000000000.0f
#define MTOT (BB * SS)

// ---------------- scratch (device globals) ----------------
__device__ float g_xq[(size_t)MTOT * NH * HD];
__device__ float g_xk[(size_t)MTOT * NKVH * HD];
__device__ float g_xv[(size_t)MTOT * NKVH * HD];
__device__ __nv_bfloat16 g_xh[(size_t)MTOT * DD];
__device__ __nv_bfloat16 g_xl[(size_t)MTOT * DD];
__device__ __nv_bfloat16 g_wqh[(size_t)DD * DD];
__device__ __nv_bfloat16 g_wql[(size_t)DD * DD];
__device__ __nv_bfloat16 g_wkh[(size_t)DD * NKVH * HD];
__device__ __nv_bfloat16 g_wkl[(size_t)DD * NKVH * HD];
__device__ __nv_bfloat16 g_wvh[(size_t)DD * NKVH * HD];
__device__ __nv_bfloat16 g_wvl[(size_t)DD * NKVH * HD];
__device__ __nv_bfloat16 g_woh[(size_t)DD * DD];
__device__ __nv_bfloat16 g_wol[(size_t)DD * DD];
__device__ __nv_bfloat16 g_ah[(size_t)MTOT * DD];
__device__ __nv_bfloat16 g_al[(size_t)MTOT * DD];

// ---------------- helpers ----------------
__device__ __forceinline__ void cpa16(uint32_t s, const void* g) {
    asm volatile("cp.async.cg.shared.global [%0], [%1], 16;" :: "r"(s), "l"(g));
}
__device__ __forceinline__ void ldmx4(uint32_t& r0, uint32_t& r1, uint32_t& r2, uint32_t& r3,
                                      uint32_t a) {
    asm volatile("ldmatrix.sync.aligned.m8n8.x4.shared.b16 {%0,%1,%2,%3}, [%4];"
                 : "=r"(r0), "=r"(r1), "=r"(r2), "=r"(r3) : "r"(a));
}

// ---------------- pre-pass: fp32 -> bf16 hi/lo (same layout) ----------------
__global__ void split_kernel(const float4* __restrict__ in,
                             __nv_bfloat16* __restrict__ hi,
                             __nv_bfloat16* __restrict__ lo, int n4) {
    int i = blockIdx.x * blockDim.x + threadIdx.x;
    if (i >= n4) return;
    float4 v = in[i];
    __nv_bfloat16 h0 = __float2bfloat16(v.x), h1 = __float2bfloat16(v.y);
    __nv_bfloat16 h2 = __float2bfloat16(v.z), h3 = __float2bfloat16(v.w);
    __nv_bfloat16 l0 = __float2bfloat16(v.x - __bfloat162float(h0));
    __nv_bfloat16 l1 = __float2bfloat16(v.y - __bfloat162float(h1));
    __nv_bfloat16 l2 = __float2bfloat16(v.z - __bfloat162float(h2));
    __nv_bfloat16 l3 = __float2bfloat16(v.w - __bfloat162float(h3));
    __nv_bfloat162* hp = (__nv_bfloat162*)(hi + (size_t)i * 4);
    __nv_bfloat162* lp = (__nv_bfloat162*)(lo + (size_t)i * 4);
    hp[0] = __halves2bfloat162(h0, h1);
    hp[1] = __halves2bfloat162(h2, h3);
    lp[0] = __halves2bfloat162(l0, l1);
    lp[1] = __halves2bfloat162(l2, l3);
}

// ---------------- pre-pass: W[K,N] fp32 -> Wt[N,K] bf16 hi/lo ----------------
__global__ void tsplit_kernel(const float* __restrict__ W,
                              __nv_bfloat16* __restrict__ Th,
                              __nv_bfloat16* __restrict__ Tl, int K, int N) {
    __shared__ float tile[32][33];
    const int tx = threadIdx.x, ty = threadIdx.y;
    const int nb = blockIdx.x * 32, kb = blockIdx.y * 32;
#pragma unroll
    for (int i = 0; i < 32; i += 8)
        tile[ty + i][tx] = W[(size_t)(kb + ty + i) * N + nb + tx];
    __syncthreads();
#pragma unroll
    for (int i = 0; i < 32; i += 8) {
        float v = tile[tx][ty + i];
        __nv_bfloat16 h = __float2bfloat16(v);
        __nv_bfloat16 l = __float2bfloat16(v - __bfloat162float(h));
        size_t o = (size_t)(nb + ty + i) * K + kb + tx;
        Th[o] = h;
        Tl[o] = l;
    }
}

// ---------------- bf16x3 HMMA GEMM ----------------
#define GM 128
#define GN 128
#define GK 32
#define APAD 40
#define REGE (128 * APAD)
#define STAGEE (4 * REGE)
#define GSMEM (2 * STAGEE * 2)

__device__ __forceinline__ void hmma(float* c, const uint32_t* a, const uint32_t* b) {
    asm volatile(
        "mma.sync.aligned.m16n8k16.row.col.f32.bf16.bf16.f32 "
        "{%0,%1,%2,%3}, {%4,%5,%6,%7}, {%8,%9}, {%0,%1,%2,%3};"
        : "+f"(c[0]), "+f"(c[1]), "+f"(c[2]), "+f"(c[3])
        : "r"(a[0]), "r"(a[1]), "r"(a[2]), "r"(a[3]), "r"(b[0]), "r"(b[1]));
}

__global__ __launch_bounds__(256, 2) void hgemm3(
    const __nv_bfloat16* __restrict__ Ah, const __nv_bfloat16* __restrict__ Al,
    const __nv_bfloat16* __restrict__ Bh, const __nv_bfloat16* __restrict__ Bl,
    float* __restrict__ C, int M, int N, int K)
{
    extern __shared__ __align__(16) __nv_bfloat16 sm[];
    const uint32_t sb = (uint32_t)__cvta_generic_to_shared(sm);
    const int tid = threadIdx.x;
    const int lane = tid & 31;
    const int wid = tid >> 5;
    const int g = lane >> 2;
    const int tg = lane & 3;
    const int wm = (wid >> 2) * 64;
    const int wn = (wid & 3) * 32;
    const int row0 = blockIdx.y * GM;
    const int col0 = blockIdx.x * GN;

    // ldmatrix lane->row/col mapping
    const int lt = lane >> 3, lr = lane & 7;
    const int arow = (lt & 1) * 8 + lr, acol = (lt >> 1) * 8;
    const int brow = (lt >> 1) * 8 + lr, bcol = (lt & 1) * 8;

    // loader mapping
    const int lreg = tid >> 6;
    const int lu = tid & 63;
    const __nv_bfloat16* base = (lreg == 0) ? Ah : (lreg == 1) ? Al : (lreg == 2) ? Bh : Bl;
    const int r0 = (lreg < 2) ? row0 : col0;

    float acc[4][4][4];
#pragma unroll
    for (int i = 0; i < 4; i++)
#pragma unroll
        for (int j = 0; j < 4; j++)
#pragma unroll
            for (int r = 0; r < 4; r++) acc[i][j][r] = 0.0f;

#define LOADSTAGE(s, k0)                                                          \
    do {                                                                          \
        const uint32_t d0 = sb + ((s) * STAGEE + lreg * REGE) * 2;                \
        _Pragma("unroll")                                                         \
        for (int it = 0; it < 8; it++) {                                          \
            int chunk = it * 64 + lu;                                             \
            int row = chunk >> 2;                                                 \
            int cc = chunk & 3;                                                   \
            cpa16(d0 + (uint32_t)(row * APAD + cc * 8) * 2,                       \
                  base + (size_t)(r0 + row) * K + (k0) + cc * 8);                 \
        }                                                                         \
        asm volatile("cp.async.commit_group;");                                   \
    } while (0)

    const int T = K / GK;
    LOADSTAGE(0, 0);

    for (int t = 0; t < T; t++) {
        __syncthreads();
        if (t + 1 < T) {
            LOADSTAGE((t + 1) & 1, (t + 1) * GK);
            asm volatile("cp.async.wait_group 1;");
        } else {
            asm volatile("cp.async.wait_group 0;");
        }
        __syncthreads();

        const int s = t & 1;
        const uint32_t sAh = sb + (s * STAGEE) * 2;
        const uint32_t sAl = sAh + REGE * 2;
        const uint32_t sBh = sAl + REGE * 2;
        const uint32_t sBl = sBh + REGE * 2;

#pragma unroll
        for (int ks = 0; ks < GK; ks += 16) {
            uint32_t bh[4][2], bl[4][2];
#pragma unroll
            for (int ntp = 0; ntp < 2; ntp++) {
                uint32_t boff = (uint32_t)((wn + ntp * 16 + brow) * APAD + ks + bcol) * 2;
                ldmx4(bh[2 * ntp][0], bh[2 * ntp][1], bh[2 * ntp + 1][0], bh[2 * ntp + 1][1],
                      sBh + boff);
                ldmx4(bl[2 * ntp][0], bl[2 * ntp][1], bl[2 * ntp + 1][0], bl[2 * ntp + 1][1],
                      sBl + boff);
            }
#pragma unroll
            for (int mt = 0; mt < 4; mt++) {
                uint32_t aoff = (uint32_t)((wm + mt * 16 + arow) * APAD + ks + acol) * 2;
                uint32_t ah[4], al[4];
                ldmx4(ah[0], ah[1], ah[2], ah[3], sAh + aoff);
                ldmx4(al[0], al[1], al[2], al[3], sAl + aoff);
#pragma unroll
                for (int nt = 0; nt < 4; nt++) {
                    hmma(acc[mt][nt], ah, bh[nt]);
                    hmma(acc[mt][nt], ah, bl[nt]);
                    hmma(acc[mt][nt], al, bh[nt]);
                }
            }
        }
    }

#pragma unroll
    for (int mt = 0; mt < 4; mt++) {
#pragma unroll
        for (int nt = 0; nt < 4; nt++) {
            int r = row0 + wm + mt * 16 + g;
            int c = col0 + wn + nt * 8 + tg * 2;
            *(float2*)&C[(size_t)r * N + c] = make_float2(acc[mt][nt][0], acc[mt][nt][1]);
            *(float2*)&C[(size_t)(r + 8) * N + c] = make_float2(acc[mt][nt][2], acc[mt][nt][3]);
        }
    }
#undef LOADSTAGE
}

// ---------------- RoPE (interleaved pairs), in place ----------------
__global__ void rope_kernel(float* __restrict__ data,
                            const float* __restrict__ cosf,
                            const float* __restrict__ sinf,
                            int nheads)
{
    size_t idx = (size_t)blockIdx.x * blockDim.x + threadIdx.x;
    size_t total = (size_t)BB * SS * nheads * (HD / 2);
    if (idx >= total) return;
    int i = (int)(idx % (HD / 2));
    size_t rem = idx / (HD / 2);
    int hh = (int)(rem % nheads);
    size_t bs = rem / nheads;
    int s = (int)(bs % SS);
    float c = cosf[(size_t)s * (HD / 2) + i];
    float sn = sinf[(size_t)s * (HD / 2) + i];
    float* p = data + (bs * nheads + hh) * HD + 2 * i;
    float x1 = p[0], x2 = p[1];
    p[0] = x1 * c - x2 * sn;
    p[1] = x1 * sn + x2 * c;
}

// ---------------- cache fill ----------------
__global__ void cache_kernel(const float* __restrict__ xk, const float* __restrict__ xv,
                             float* __restrict__ ck, float* __restrict__ cv)
{
    size_t idx = (size_t)blockIdx.x * blockDim.x + threadIdx.x;
    size_t total = (size_t)BB * SWIN * NKVH * HD;
    if (idx >= total) return;
    int d = (int)(idx % HD);
    size_t r = idx / HD;
    int kvh = (int)(r % NKVH); r /= NKVH;
    int s = (int)(r % SWIN);
    int b = (int)(r / SWIN);
    float kval = 0.0f, vval = 0.0f;
    if (s < SS) {
        size_t src = (((size_t)b * SS + s) * NKVH + kvh) * HD + d;
        kval = xk[src];
        vval = xv[src];
    }
    ck[idx] = kval;
    cv[idx] = vval;
}

// ---------------- flash v2: quad-per-query, smem-staged K/V ----------------
// block: 128 threads (4 warps) = 32 queries; warp = 8 queries x 4-lane quads.
// dyn smem: K[2][32][128] fp32 then V[2][32][128] fp32 = 64KB.
#define FKB 16384                 // one K/V buffer in bytes
#define FSMEM (4 * FKB)

__global__ __launch_bounds__(128) void flash2_kernel(
    const float* __restrict__ xq, const float* __restrict__ xk,
    const float* __restrict__ xv,
    __nv_bfloat16* __restrict__ outh, __nv_bfloat16* __restrict__ outl)
{
    extern __shared__ __align__(16) float fsm[];
    const uint32_t sb = (uint32_t)__cvta_generic_to_shared(fsm);

    const int bx = blockIdx.x;            // q-tile (32 queries)
    const int h = blockIdx.y;
    const int b = blockIdx.z;
    const int tid = threadIdx.x;
    const int wid = tid >> 5;
    const int lane = tid & 31;
    const int m = lane & 3;               // quad member: owns chunks c ≡ m (mod 4)
    const int q = bx * 32 + wid * 8 + (lane >> 2);
    const int kvh = h / KVREP;

    // Q in registers: 8 float4 chunks (c = 4j + m)
    const float* qptr = xq + (((size_t)b * SS + q) * NH + h) * HD;
    float4 qf[8];
#pragma unroll
    for (int j = 0; j < 8; j++)
        qf[j] = *(const float4*)(qptr + (4 * j + m) * 4);

    float4 of[8];
#pragma unroll
    for (int j = 0; j < 8; j++) of[j] = make_float4(0.f, 0.f, 0.f, 0.f);
    float mx = -1e30f, lsum = 0.0f;

    const float* kbase = xk + (((size_t)b * SS) * NKVH + kvh) * HD;
    const float* vbase = xv + (((size_t)b * SS) * NKVH + kvh) * HD;
    const int ntiles = bx + 1;

    // prefetch tile 0
    {
#pragma unroll
        for (int it = 0; it < 8; it++) {
            int idx = it * 128 + tid;
            int row = idx >> 5, cc = idx & 31;
            size_t go = (size_t)row * NKVH * HD + cc * 4;
            cpa16(sb + (uint32_t)(row * 512 + cc * 16), kbase + go);
            cpa16(sb + 2 * FKB + (uint32_t)(row * 512 + cc * 16), vbase + go);
        }
        asm volatile("cp.async.commit_group;");
    }

    for (int kt = 0; kt < ntiles; kt++) {
        const int buf = kt & 1;
        if (kt + 1 < ntiles) {
            const int nb = (kt + 1) & 1;
            const float* kn = kbase + (size_t)(kt + 1) * 32 * NKVH * HD;
            const float* vn = vbase + (size_t)(kt + 1) * 32 * NKVH * HD;
#pragma unroll
            for (int it = 0; it < 8; it++) {
                int idx = it * 128 + tid;
                int row = idx >> 5, cc = idx & 31;
                size_t go = (size_t)row * NKVH * HD + cc * 4;
                cpa16(sb + (uint32_t)(nb * FKB + row * 512 + cc * 16), kn + go);
                cpa16(sb + 2 * FKB + (uint32_t)(nb * FKB + row * 512 + cc * 16), vn + go);
            }
            asm volatile("cp.async.commit_group;");
            asm volatile("cp.async.wait_group 1;");
        } else {
            asm volatile("cp.async.wait_group 0;");
        }
        __syncthreads();

        const float* Ksf = fsm + buf * 4096;
        const float* Vsf = fsm + 8192 + buf * 4096;
        const int k0 = kt * 32;

        float sreg[32];
        float tmax = -1e30f;
#pragma unroll
        for (int k = 0; k < 32; k++) {
            const float* kr = Ksf + k * 128;
            float s0 = 0.f, s1 = 0.f;
#pragma unroll
            for (int j = 0; j < 8; j += 2) {
                float4 a = *(const float4*)(kr + (4 * j + m) * 4);
                float4 c = *(const float4*)(kr + (4 * (j + 1) + m) * 4);
                s0 += qf[j].x * a.x + qf[j].y * a.y + qf[j].z * a.z + qf[j].w * a.w;
                s1 += qf[j + 1].x * c.x + qf[j + 1].y * c.y + qf[j + 1].z * c.z + qf[j + 1].w * c.w;
            }
            float part = s0 + s1;
            part += __shfl_xor_sync(0xFFFFFFFFu, part, 1);
            part += __shfl_xor_sync(0xFFFFFFFFu, part, 2);
            float sc = part * ATT_SCALE + ((k0 + k) > q ? NEGBIG : 0.0f);
            sreg[k] = sc;
            tmax = fmaxf(tmax, sc);
        }

        float mnew = fmaxf(mx, tmax);
        float corr = __expf(mx - mnew);
        lsum *= corr;
#pragma unroll
        for (int j = 0; j < 8; j++) {
            of[j].x *= corr; of[j].y *= corr; of[j].z *= corr; of[j].w *= corr;
        }

#pragma unroll
        for (int k = 0; k < 32; k++) {
            float p = __expf(sreg[k] - mnew);
            lsum += p;
            const float* vr = Vsf + k * 128;
#pragma unroll
            for (int j = 0; j < 8; j++) {
                float4 v = *(const float4*)(vr + (4 * j + m) * 4);
                of[j].x += p * v.x; of[j].y += p * v.y;
                of[j].z += p * v.z; of[j].w += p * v.w;
            }
        }
        mx = mnew;
        __syncthreads();
    }

    const float inv = 1.0f / lsum;
    size_t obase = ((size_t)b * SS + q) * (size_t)(NH * HD) + h * HD;
#pragma unroll
    for (int j = 0; j < 8; j++) {
        float r0 = of[j].x * inv, r1 = of[j].y * inv;
        float r2 = of[j].z * inv, r3 = of[j].w * inv;
        __nv_bfloat16 h0 = __float2bfloat16(r0), h1 = __float2bfloat16(r1);
        __nv_bfloat16 h2 = __float2bfloat16(r2), h3 = __float2bfloat16(r3);
        __nv_bfloat16 l0 = __float2bfloat16(r0 - __bfloat162float(h0));
        __nv_bfloat16 l1 = __float2bfloat16(r1 - __bfloat162float(h1));
        __nv_bfloat16 l2 = __float2bfloat16(r2 - __bfloat162float(h2));
        __nv_bfloat16 l3 = __float2bfloat16(r3 - __bfloat162float(h3));
        size_t oo = obase + (4 * j + m) * 4;
        __nv_bfloat162* hp = (__nv_bfloat162*)(outh + oo);
        __nv_bfloat162* lp = (__nv_bfloat162*)(outl + oo);
        hp[0] = __halves2bfloat162(h0, h1);
        hp[1] = __halves2bfloat162(h2, h3);
        lp[0] = __halves2bfloat162(l0, l1);
        lp[1] = __halves2bfloat162(l2, l3);
    }
}

// ---------------- launch ----------------
extern "C" void kernel_launch(void* const* d_in, const int* in_sizes, int n_in,
                              void* d_out, int out_size)
{
    const float* x    = (const float*)d_in[0];
    const float* cosf = (const float*)d_in[1];
    const float* sinf = (const float*)d_in[2];
    const float* wq = (const float*)d_in[7];
    const float* wk = (const float*)d_in[8];
    const float* wv = (const float*)d_in[9];
    const float* wo = (const float*)d_in[10];

    float* out = (float*)d_out;
    float* ck = out + (size_t)MTOT * DD;
    float* cv = ck + (size_t)BB * SWIN * NKVH * HD;

    float *xq, *xk, *xv;
    __nv_bfloat16 *xh, *xl, *wqh, *wql, *wkh, *wkl, *wvh, *wvl, *woh, *wol, *ah, *al;
    cudaGetSymbolAddress((void**)&xq, g_xq);
    cudaGetSymbolAddress((void**)&xk, g_xk);
    cudaGetSymbolAddress((void**)&xv, g_xv);
    cudaGetSymbolAddress((void**)&xh, g_xh);
    cudaGetSymbolAddress((void**)&xl, g_xl);
    cudaGetSymbolAddress((void**)&wqh, g_wqh);
    cudaGetSymbolAddress((void**)&wql, g_wql);
    cudaGetSymbolAddress((void**)&wkh, g_wkh);
    cudaGetSymbolAddress((void**)&wkl, g_wkl);
    cudaGetSymbolAddress((void**)&wvh, g_wvh);
    cudaGetSymbolAddress((void**)&wvl, g_wvl);
    cudaGetSymbolAddress((void**)&woh, g_woh);
    cudaGetSymbolAddress((void**)&wol, g_wol);
    cudaGetSymbolAddress((void**)&ah, g_ah);
    cudaGetSymbolAddress((void**)&al, g_al);

    cudaFuncSetAttribute(hgemm3, cudaFuncAttributeMaxDynamicSharedMemorySize, GSMEM);
    cudaFuncSetAttribute(flash2_kernel, cudaFuncAttributeMaxDynamicSharedMemorySize, FSMEM);

    // pre-pass: split x; transpose+split weights
    {
        int n4 = (int)((size_t)MTOT * DD / 4);
        split_kernel<<<(n4 + 255) / 256, 256>>>((const float4*)x, xh, xl, n4);
        dim3 blk(32, 8);
        tsplit_kernel<<<dim3(DD / 32, DD / 32), blk>>>(wq, wqh, wql, DD, DD);
        tsplit_kernel<<<dim3((NKVH * HD) / 32, DD / 32), blk>>>(wk, wkh, wkl, DD, NKVH * HD);
        tsplit_kernel<<<dim3((NKVH * HD) / 32, DD / 32), blk>>>(wv, wvh, wvl, DD, NKVH * HD);
        tsplit_kernel<<<dim3(DD / 32, DD / 32), blk>>>(wo, woh, wol, NH * HD, DD);
    }

    // QKV projections
    hgemm3<<<dim3(DD / GN, MTOT / GM), 256, GSMEM>>>(xh, xl, wqh, wql, xq, MTOT, DD, DD);
    hgemm3<<<dim3((NKVH * HD) / GN, MTOT / GM), 256, GSMEM>>>(xh, xl, wkh, wkl, xk, MTOT, NKVH * HD, DD);
    hgemm3<<<dim3((NKVH * HD) / GN, MTOT / GM), 256, GSMEM>>>(xh, xl, wvh, wvl, xv, MTOT, NKVH * HD, DD);

    // RoPE
    {
        size_t tq = (size_t)BB * SS * NH * (HD / 2);
        rope_kernel<<<(unsigned)((tq + 255) / 256), 256>>>(xq, cosf, sinf, NH);
        size_t tk = (size_t)BB * SS * NKVH * (HD / 2);
        rope_kernel<<<(unsigned)((tk + 255) / 256), 256>>>(xk, cosf, sinf, NKVH);
    }

    // cache outputs
    {
        size_t tc = (size_t)BB * SWIN * NKVH * HD;
        cache_kernel<<<(unsigned)((tc + 255) / 256), 256>>>(xk, xv, ck, cv);
    }

    // attention (flash v2)
    {
        dim3 gf(SS / 32, NH, BB);
        flash2_kernel<<<gf, 128, FSMEM>>>(xq, xk, xv, ah, al);
    }

    // output projection
    hgemm3<<<dim3(DD / GN, MTOT / GM), 256, GSMEM>>>(ah, al, woh, wol, out, MTOT, DD, NH * HD);
}

// round 6
// speedup vs baseline: 2.3420x; 1.1108x over previous
#include <cuda_runtime.h>
#include <cuda_bf16.h>
#include <cstdint>

#define BB 2
#define SS 2048
#define DD 4096
#define NH 32
#define NKVH 8
#define HD 128
#define SWIN 4096
#define KVREP 4
#define ATT_SCALE 0.08838834764831845f
#define NEGBIG -1000000000.0f
#define MTOT (BB * SS)

#define QX 5461.3333333f          /* 32768/6  : x range +-6   */
#define QW 262144.0f              /* 32768/0.125 : w range +-0.125 */
#define INV_SASB 6.9849193096160889e-10  /* (6/32768)*(0.125/32768) */

// ---------------- scratch (device globals) ----------------
__device__ float g_xq[(size_t)MTOT * NH * HD];
__device__ float g_xk[(size_t)MTOT * NKVH * HD];
__device__ float g_xv[(size_t)MTOT * NKVH * HD];
// int8 limbs for x and qkv weights
__device__ int8_t g_x8h[(size_t)MTOT * DD];
__device__ int8_t g_x8l[(size_t)MTOT * DD];
__device__ int8_t g_wq8h[(size_t)DD * DD];
__device__ int8_t g_wq8l[(size_t)DD * DD];
__device__ int8_t g_wk8h[(size_t)DD * NKVH * HD];
__device__ int8_t g_wk8l[(size_t)DD * NKVH * HD];
__device__ int8_t g_wv8h[(size_t)DD * NKVH * HD];
__device__ int8_t g_wv8l[(size_t)DD * NKVH * HD];
// bf16 limbs for wo path
__device__ __nv_bfloat16 g_woh[(size_t)DD * DD];
__device__ __nv_bfloat16 g_wol[(size_t)DD * DD];
__device__ __nv_bfloat16 g_ah[(size_t)MTOT * DD];
__device__ __nv_bfloat16 g_al[(size_t)MTOT * DD];

// ---------------- helpers ----------------
__device__ __forceinline__ void cpa16(uint32_t s, const void* g) {
    asm volatile("cp.async.cg.shared.global [%0], [%1], 16;" :: "r"(s), "l"(g));
}
__device__ __forceinline__ void ldmx4(uint32_t& r0, uint32_t& r1, uint32_t& r2, uint32_t& r3,
                                      uint32_t a) {
    asm volatile("ldmatrix.sync.aligned.m8n8.x4.shared.b16 {%0,%1,%2,%3}, [%4];"
                 : "=r"(r0), "=r"(r1), "=r"(r2), "=r"(r3) : "r"(a));
}
__device__ __forceinline__ void q16split(float v, float q, int8_t& hi, int8_t& lo) {
    int a = __float2int_rn(v * q);
    a = max(-32767, min(32639, a));
    int h = (a + 128) >> 8;
    hi = (int8_t)h;
    lo = (int8_t)(a - (h << 8));
}

// ---------------- quantize x: fp32[M,K] -> s8 hi/lo [M,K] ----------------
__global__ void quantx_kernel(const float4* __restrict__ in,
                              int8_t* __restrict__ hi, int8_t* __restrict__ lo, int n4) {
    int i = blockIdx.x * blockDim.x + threadIdx.x;
    if (i >= n4) return;
    float4 v = in[i];
    int8_t h[4], l[4];
    q16split(v.x, QX, h[0], l[0]);
    q16split(v.y, QX, h[1], l[1]);
    q16split(v.z, QX, h[2], l[2]);
    q16split(v.w, QX, h[3], l[3]);
    *(char4*)(hi + (size_t)i * 4) = make_char4(h[0], h[1], h[2], h[3]);
    *(char4*)(lo + (size_t)i * 4) = make_char4(l[0], l[1], l[2], l[3]);
}

// ---------------- quantize+transpose weights: W[K,N] fp32 -> [N,K] s8 hi/lo ----------------
__global__ void qtsplit_kernel(const float* __restrict__ W,
                               int8_t* __restrict__ Th, int8_t* __restrict__ Tl,
                               int K, int N) {
    __shared__ float tile[32][33];
    const int tx = threadIdx.x, ty = threadIdx.y;
    const int nb = blockIdx.x * 32, kb = blockIdx.y * 32;
#pragma unroll
    for (int i = 0; i < 32; i += 8)
        tile[ty + i][tx] = W[(size_t)(kb + ty + i) * N + nb + tx];
    __syncthreads();
#pragma unroll
    for (int i = 0; i < 32; i += 8) {
        int8_t h, l;
        q16split(tile[tx][ty + i], QW, h, l);
        size_t o = (size_t)(nb + ty + i) * K + kb + tx;
        Th[o] = h;
        Tl[o] = l;
    }
}

// ---------------- bf16 transpose+split for wo ----------------
__global__ void tsplit_kernel(const float* __restrict__ W,
                              __nv_bfloat16* __restrict__ Th,
                              __nv_bfloat16* __restrict__ Tl, int K, int N) {
    __shared__ float tile[32][33];
    const int tx = threadIdx.x, ty = threadIdx.y;
    const int nb = blockIdx.x * 32, kb = blockIdx.y * 32;
#pragma unroll
    for (int i = 0; i < 32; i += 8)
        tile[ty + i][tx] = W[(size_t)(kb + ty + i) * N + nb + tx];
    __syncthreads();
#pragma unroll
    for (int i = 0; i < 32; i += 8) {
        float v = tile[tx][ty + i];
        __nv_bfloat16 h = __float2bfloat16(v);
        __nv_bfloat16 l = __float2bfloat16(v - __bfloat162float(h));
        size_t o = (size_t)(nb + ty + i) * K + kb + tx;
        Th[o] = h;
        Tl[o] = l;
    }
}

// ---------------- int8 3-pass IMMA GEMM ----------------
// C[M,N](fp32) = sa*sb*(65536*Ah.Bh + 256*(Ah.Bl + Al.Bh)), A [M,K], B [N,K] s8.
#define IBM 128
#define IBN 64
#define IGK 64
#define IAPAD 80                       // bytes per row (64 data + pad)
#define IAREG (128 * IAPAD)            // 10240
#define IBREG (64 * IAPAD)             // 5120
#define ISTAGE (2 * IAREG + 2 * IBREG) // 30720
#define ISMEM (2 * ISTAGE)             // 61440

__device__ __forceinline__ void imma(int* c, const uint32_t* a, const uint32_t* b) {
    asm volatile(
        "mma.sync.aligned.m16n8k32.row.col.s32.s8.s8.s32 "
        "{%0,%1,%2,%3}, {%4,%5,%6,%7}, {%8,%9}, {%0,%1,%2,%3};"
        : "+r"(c[0]), "+r"(c[1]), "+r"(c[2]), "+r"(c[3])
        : "r"(a[0]), "r"(a[1]), "r"(a[2]), "r"(a[3]), "r"(b[0]), "r"(b[1]));
}

__global__ __launch_bounds__(256, 2) void igemm3(
    const int8_t* __restrict__ Ah8, const int8_t* __restrict__ Al8,
    const int8_t* __restrict__ Bh8, const int8_t* __restrict__ Bl8,
    float* __restrict__ C, int M, int N, int K)
{
    extern __shared__ __align__(16) char ism[];
    const uint32_t sb = (uint32_t)__cvta_generic_to_shared(ism);
    const int tid = threadIdx.x;
    const int lane = tid & 31;
    const int wid = tid >> 5;
    const int g = lane >> 2;
    const int tg = lane & 3;
    const int lt = lane >> 3, lr = lane & 7;
    const int wm = (wid >> 2) * 64;          // 2 m-groups of 64
    const int wn = (wid & 3) * 16;           // 4 n-groups of 16
    const int row0 = blockIdx.y * IBM;
    const int col0 = blockIdx.x * IBN;

    // ldmatrix lane mapping (b16 view of s8 pairs)
    const int arow_l = (lt & 1) * 8 + lr;
    const int acol_b = (lt >> 1) * 16;       // bytes
    const int brow_l = (lt >> 1) * 8 + lr;
    const int bcol_b = (lt & 1) * 16;        // bytes

    // loader mapping
    const int areg = tid >> 7;               // 0=hi, 1=lo
    const int arow = tid & 127;
    const int brow = (tid >> 1) & 63;
    const int bch = (tid & 1) * 2;
    const int8_t* Asrc = (areg ? Al8 : Ah8) + (size_t)(row0 + arow) * K;
    const int8_t* Bsrc = (areg ? Bl8 : Bh8) + (size_t)(col0 + brow) * K;

    int hh[4][2][4], mid[4][2][4];
#pragma unroll
    for (int i = 0; i < 4; i++)
#pragma unroll
        for (int j = 0; j < 2; j++)
#pragma unroll
            for (int r = 0; r < 4; r++) { hh[i][j][r] = 0; mid[i][j][r] = 0; }

#define ILOAD(s, k0)                                                              \
    do {                                                                          \
        uint32_t ad = sb + (s) * ISTAGE + areg * IAREG + arow * IAPAD;            \
        uint32_t bd = sb + (s) * ISTAGE + 2 * IAREG + areg * IBREG + brow * IAPAD; \
        _Pragma("unroll")                                                         \
        for (int c = 0; c < 4; c++) cpa16(ad + c * 16, Asrc + (k0) + c * 16);     \
        _Pragma("unroll")                                                         \
        for (int c = 0; c < 2; c++)                                               \
            cpa16(bd + (bch + c) * 16, Bsrc + (k0) + (bch + c) * 16);             \
        asm volatile("cp.async.commit_group;");                                   \
    } while (0)

    const int T = K / IGK;
    ILOAD(0, 0);

    for (int t = 0; t < T; t++) {
        __syncthreads();
        if (t + 1 < T) {
            ILOAD((t + 1) & 1, (t + 1) * IGK);
            asm volatile("cp.async.wait_group 1;");
        } else {
            asm volatile("cp.async.wait_group 0;");
        }
        __syncthreads();

        const int s = t & 1;
        const uint32_t sAh = sb + s * ISTAGE;
        const uint32_t sAl = sAh + IAREG;
        const uint32_t sBh = sAl + IAREG;
        const uint32_t sBl = sBh + IBREG;

#pragma unroll
        for (int ks = 0; ks < 2; ks++) {
            uint32_t bh[2][2], bl[2][2];
            {
                uint32_t boff = (uint32_t)((wn + brow_l) * IAPAD + ks * 32 + bcol_b);
                ldmx4(bh[0][0], bh[0][1], bh[1][0], bh[1][1], sBh + boff);
                ldmx4(bl[0][0], bl[0][1], bl[1][0], bl[1][1], sBl + boff);
            }
#pragma unroll
            for (int mt = 0; mt < 4; mt++) {
                uint32_t aoff = (uint32_t)((wm + mt * 16 + arow_l) * IAPAD + ks * 32 + acol_b);
                uint32_t ah[4], al[4];
                ldmx4(ah[0], ah[1], ah[2], ah[3], sAh + aoff);
                ldmx4(al[0], al[1], al[2], al[3], sAl + aoff);
#pragma unroll
                for (int nt = 0; nt < 2; nt++) {
                    imma(hh[mt][nt], ah, bh[nt]);
                    imma(mid[mt][nt], ah, bl[nt]);
                    imma(mid[mt][nt], al, bh[nt]);
                }
            }
        }
    }

#pragma unroll
    for (int mt = 0; mt < 4; mt++) {
#pragma unroll
        for (int nt = 0; nt < 2; nt++) {
            int r = row0 + wm + mt * 16 + g;
            int c = col0 + wn + nt * 8 + tg * 2;
            float f0 = (float)((65536.0 * hh[mt][nt][0] + 256.0 * mid[mt][nt][0]) * INV_SASB);
            float f1 = (float)((65536.0 * hh[mt][nt][1] + 256.0 * mid[mt][nt][1]) * INV_SASB);
            float f2 = (float)((65536.0 * hh[mt][nt][2] + 256.0 * mid[mt][nt][2]) * INV_SASB);
            float f3 = (float)((65536.0 * hh[mt][nt][3] + 256.0 * mid[mt][nt][3]) * INV_SASB);
            *(float2*)&C[(size_t)r * N + c] = make_float2(f0, f1);
            *(float2*)&C[(size_t)(r + 8) * N + c] = make_float2(f2, f3);
        }
    }
#undef ILOAD
}

// ---------------- bf16x3 HMMA GEMM (wo path) ----------------
#define GM 128
#define GN 128
#define GK 32
#define APAD 40
#define REGE (128 * APAD)
#define STAGEE (4 * REGE)
#define GSMEM (2 * STAGEE * 2)

__device__ __forceinline__ void hmma(float* c, const uint32_t* a, const uint32_t* b) {
    asm volatile(
        "mma.sync.aligned.m16n8k16.row.col.f32.bf16.bf16.f32 "
        "{%0,%1,%2,%3}, {%4,%5,%6,%7}, {%8,%9}, {%0,%1,%2,%3};"
        : "+f"(c[0]), "+f"(c[1]), "+f"(c[2]), "+f"(c[3])
        : "r"(a[0]), "r"(a[1]), "r"(a[2]), "r"(a[3]), "r"(b[0]), "r"(b[1]));
}

__global__ __launch_bounds__(256, 2) void hgemm3(
    const __nv_bfloat16* __restrict__ Ah, const __nv_bfloat16* __restrict__ Al,
    const __nv_bfloat16* __restrict__ Bh, const __nv_bfloat16* __restrict__ Bl,
    float* __restrict__ C, int M, int N, int K)
{
    extern __shared__ __align__(16) __nv_bfloat16 sm[];
    const uint32_t sb = (uint32_t)__cvta_generic_to_shared(sm);
    const int tid = threadIdx.x;
    const int lane = tid & 31;
    const int wid = tid >> 5;
    const int g = lane >> 2;
    const int tg = lane & 3;
    const int wm = (wid >> 2) * 64;
    const int wn = (wid & 3) * 32;
    const int row0 = blockIdx.y * GM;
    const int col0 = blockIdx.x * GN;

    const int lt = lane >> 3, lr = lane & 7;
    const int arow = (lt & 1) * 8 + lr, acol = (lt >> 1) * 8;
    const int brow = (lt >> 1) * 8 + lr, bcol = (lt & 1) * 8;

    const int lreg = tid >> 6;
    const int lu = tid & 63;
    const __nv_bfloat16* base = (lreg == 0) ? Ah : (lreg == 1) ? Al : (lreg == 2) ? Bh : Bl;
    const int r0 = (lreg < 2) ? row0 : col0;

    float acc[4][4][4];
#pragma unroll
    for (int i = 0; i < 4; i++)
#pragma unroll
        for (int j = 0; j < 4; j++)
#pragma unroll
            for (int r = 0; r < 4; r++) acc[i][j][r] = 0.0f;

#define LOADSTAGE(s, k0)                                                          \
    do {                                                                          \
        const uint32_t d0 = sb + ((s) * STAGEE + lreg * REGE) * 2;                \
        _Pragma("unroll")                                                         \
        for (int it = 0; it < 8; it++) {                                          \
            int chunk = it * 64 + lu;                                             \
            int row = chunk >> 2;                                                 \
            int cc = chunk & 3;                                                   \
            cpa16(d0 + (uint32_t)(row * APAD + cc * 8) * 2,                       \
                  base + (size_t)(r0 + row) * K + (k0) + cc * 8);                 \
        }                                                                         \
        asm volatile("cp.async.commit_group;");                                   \
    } while (0)

    const int T = K / GK;
    LOADSTAGE(0, 0);

    for (int t = 0; t < T; t++) {
        __syncthreads();
        if (t + 1 < T) {
            LOADSTAGE((t + 1) & 1, (t + 1) * GK);
            asm volatile("cp.async.wait_group 1;");
        } else {
            asm volatile("cp.async.wait_group 0;");
        }
        __syncthreads();

        const int s = t & 1;
        const uint32_t sAh = sb + (s * STAGEE) * 2;
        const uint32_t sAl = sAh + REGE * 2;
        const uint32_t sBh = sAl + REGE * 2;
        const uint32_t sBl = sBh + REGE * 2;

#pragma unroll
        for (int ks = 0; ks < GK; ks += 16) {
            uint32_t bh[4][2], bl[4][2];
#pragma unroll
            for (int ntp = 0; ntp < 2; ntp++) {
                uint32_t boff = (uint32_t)((wn + ntp * 16 + brow) * APAD + ks + bcol) * 2;
                ldmx4(bh[2 * ntp][0], bh[2 * ntp][1], bh[2 * ntp + 1][0], bh[2 * ntp + 1][1],
                      sBh + boff);
                ldmx4(bl[2 * ntp][0], bl[2 * ntp][1], bl[2 * ntp + 1][0], bl[2 * ntp + 1][1],
                      sBl + boff);
            }
#pragma unroll
            for (int mt = 0; mt < 4; mt++) {
                uint32_t aoff = (uint32_t)((wm + mt * 16 + arow) * APAD + ks + acol) * 2;
                uint32_t ah[4], al[4];
                ldmx4(ah[0], ah[1], ah[2], ah[3], sAh + aoff);
                ldmx4(al[0], al[1], al[2], al[3], sAl + aoff);
#pragma unroll
                for (int nt = 0; nt < 4; nt++) {
                    hmma(acc[mt][nt], ah, bh[nt]);
                    hmma(acc[mt][nt], ah, bl[nt]);
                    hmma(acc[mt][nt], al, bh[nt]);
                }
            }
        }
    }

#pragma unroll
    for (int mt = 0; mt < 4; mt++) {
#pragma unroll
        for (int nt = 0; nt < 4; nt++) {
            int r = row0 + wm + mt * 16 + g;
            int c = col0 + wn + nt * 8 + tg * 2;
            *(float2*)&C[(size_t)r * N + c] = make_float2(acc[mt][nt][0], acc[mt][nt][1]);
            *(float2*)&C[(size_t)(r + 8) * N + c] = make_float2(acc[mt][nt][2], acc[mt][nt][3]);
        }
    }
#undef LOADSTAGE
}

// ---------------- RoPE (interleaved pairs), in place ----------------
__global__ void rope_kernel(float* __restrict__ data,
                            const float* __restrict__ cosf,
                            const float* __restrict__ sinf,
                            int nheads)
{
    size_t idx = (size_t)blockIdx.x * blockDim.x + threadIdx.x;
    size_t total = (size_t)BB * SS * nheads * (HD / 2);
    if (idx >= total) return;
    int i = (int)(idx % (HD / 2));
    size_t rem = idx / (HD / 2);
    int hh = (int)(rem % nheads);
    size_t bs = rem / nheads;
    int s = (int)(bs % SS);
    float c = cosf[(size_t)s * (HD / 2) + i];
    float sn = sinf[(size_t)s * (HD / 2) + i];
    float* p = data + (bs * nheads + hh) * HD + 2 * i;
    float x1 = p[0], x2 = p[1];
    p[0] = x1 * c - x2 * sn;
    p[1] = x1 * sn + x2 * c;
}

// ---------------- cache fill ----------------
__global__ void cache_kernel(const float* __restrict__ xk, const float* __restrict__ xv,
                             float* __restrict__ ck, float* __restrict__ cv)
{
    size_t idx = (size_t)blockIdx.x * blockDim.x + threadIdx.x;
    size_t total = (size_t)BB * SWIN * NKVH * HD;
    if (idx >= total) return;
    int d = (int)(idx % HD);
    size_t r = idx / HD;
    int kvh = (int)(r % NKVH); r /= NKVH;
    int s = (int)(r % SWIN);
    int b = (int)(r / SWIN);
    float kval = 0.0f, vval = 0.0f;
    if (s < SS) {
        size_t src = (((size_t)b * SS + s) * NKVH + kvh) * HD + d;
        kval = xk[src];
        vval = xv[src];
    }
    ck[idx] = kval;
    cv[idx] = vval;
}

// ---------------- flash v2 ----------------
#define FKB 16384
#define FSMEM (4 * FKB)

__global__ __launch_bounds__(128) void flash2_kernel(
    const float* __restrict__ xq, const float* __restrict__ xk,
    const float* __restrict__ xv,
    __nv_bfloat16* __restrict__ outh, __nv_bfloat16* __restrict__ outl)
{
    extern __shared__ __align__(16) float fsm[];
    const uint32_t sb = (uint32_t)__cvta_generic_to_shared(fsm);

    const int bx = blockIdx.x;
    const int h = blockIdx.y;
    const int b = blockIdx.z;
    const int tid = threadIdx.x;
    const int wid = tid >> 5;
    const int lane = tid & 31;
    const int m = lane & 3;
    const int q = bx * 32 + wid * 8 + (lane >> 2);
    const int kvh = h / KVREP;

    const float* qptr = xq + (((size_t)b * SS + q) * NH + h) * HD;
    float4 qf[8];
#pragma unroll
    for (int j = 0; j < 8; j++)
        qf[j] = *(const float4*)(qptr + (4 * j + m) * 4);

    float4 of[8];
#pragma unroll
    for (int j = 0; j < 8; j++) of[j] = make_float4(0.f, 0.f, 0.f, 0.f);
    float mx = -1e30f, lsum = 0.0f;

    const float* kbase = xk + (((size_t)b * SS) * NKVH + kvh) * HD;
    const float* vbase = xv + (((size_t)b * SS) * NKVH + kvh) * HD;
    const int ntiles = bx + 1;

    {
#pragma unroll
        for (int it = 0; it < 8; it++) {
            int idx = it * 128 + tid;
            int row = idx >> 5, cc = idx & 31;
            size_t go = (size_t)row * NKVH * HD + cc * 4;
            cpa16(sb + (uint32_t)(row * 512 + cc * 16), kbase + go);
            cpa16(sb + 2 * FKB + (uint32_t)(row * 512 + cc * 16), vbase + go);
        }
        asm volatile("cp.async.commit_group;");
    }

    for (int kt = 0; kt < ntiles; kt++) {
        const int buf = kt & 1;
        if (kt + 1 < ntiles) {
            const int nb = (kt + 1) & 1;
            const float* kn = kbase + (size_t)(kt + 1) * 32 * NKVH * HD;
            const float* vn = vbase + (size_t)(kt + 1) * 32 * NKVH * HD;
#pragma unroll
            for (int it = 0; it < 8; it++) {
                int idx = it * 128 + tid;
                int row = idx >> 5, cc = idx & 31;
                size_t go = (size_t)row * NKVH * HD + cc * 4;
                cpa16(sb + (uint32_t)(nb * FKB + row * 512 + cc * 16), kn + go);
                cpa16(sb + 2 * FKB + (uint32_t)(nb * FKB + row * 512 + cc * 16), vn + go);
            }
            asm volatile("cp.async.commit_group;");
            asm volatile("cp.async.wait_group 1;");
        } else {
            asm volatile("cp.async.wait_group 0;");
        }
        __syncthreads();

        const float* Ksf = fsm + buf * 4096;
        const float* Vsf = fsm + 8192 + buf * 4096;
        const int k0 = kt * 32;

        float sreg[32];
        float tmax = -1e30f;
#pragma unroll
        for (int k = 0; k < 32; k++) {
            const float* kr = Ksf + k * 128;
            float s0 = 0.f, s1 = 0.f;
#pragma unroll
            for (int j = 0; j < 8; j += 2) {
                float4 a = *(const float4*)(kr + (4 * j + m) * 4);
                float4 c = *(const float4*)(kr + (4 * (j + 1) + m) * 4);
                s0 += qf[j].x * a.x + qf[j].y * a.y + qf[j].z * a.z + qf[j].w * a.w;
                s1 += qf[j + 1].x * c.x + qf[j + 1].y * c.y + qf[j + 1].z * c.z + qf[j + 1].w * c.w;
            }
            float part = s0 + s1;
            part += __shfl_xor_sync(0xFFFFFFFFu, part, 1);
            part += __shfl_xor_sync(0xFFFFFFFFu, part, 2);
            float sc = part * ATT_SCALE + ((k0 + k) > q ? NEGBIG : 0.0f);
            sreg[k] = sc;
            tmax = fmaxf(tmax, sc);
        }

        float mnew = fmaxf(mx, tmax);
        float corr = __expf(mx - mnew);
        lsum *= corr;
#pragma unroll
        for (int j = 0; j < 8; j++) {
            of[j].x *= corr; of[j].y *= corr; of[j].z *= corr; of[j].w *= corr;
        }

#pragma unroll
        for (int k = 0; k < 32; k++) {
            float p = __expf(sreg[k] - mnew);
            lsum += p;
            const float* vr = Vsf + k * 128;
#pragma unroll
            for (int j = 0; j < 8; j++) {
                float4 v = *(const float4*)(vr + (4 * j + m) * 4);
                of[j].x += p * v.x; of[j].y += p * v.y;
                of[j].z += p * v.z; of[j].w += p * v.w;
            }
        }
        mx = mnew;
        __syncthreads();
    }

    const float inv = 1.0f / lsum;
    size_t obase = ((size_t)b * SS + q) * (size_t)(NH * HD) + h * HD;
#pragma unroll
    for (int j = 0; j < 8; j++) {
        float r0 = of[j].x * inv, r1 = of[j].y * inv;
        float r2 = of[j].z * inv, r3 = of[j].w * inv;
        __nv_bfloat16 h0 = __float2bfloat16(r0), h1 = __float2bfloat16(r1);
        __nv_bfloat16 h2 = __float2bfloat16(r2), h3 = __float2bfloat16(r3);
        __nv_bfloat16 l0 = __float2bfloat16(r0 - __bfloat162float(h0));
        __nv_bfloat16 l1 = __float2bfloat16(r1 - __bfloat162float(h1));
        __nv_bfloat16 l2 = __float2bfloat16(r2 - __bfloat162float(h2));
        __nv_bfloat16 l3 = __float2bfloat16(r3 - __bfloat162float(h3));
        size_t oo = obase + (4 * j + m) * 4;
        __nv_bfloat162* hp = (__nv_bfloat162*)(outh + oo);
        __nv_bfloat162* lp = (__nv_bfloat162*)(outl + oo);
        hp[0] = __halves2bfloat162(h0, h1);
        hp[1] = __halves2bfloat162(h2, h3);
        lp[0] = __halves2bfloat162(l0, l1);
        lp[1] = __halves2bfloat162(l2, l3);
    }
}

// ---------------- launch ----------------
extern "C" void kernel_launch(void* const* d_in, const int* in_sizes, int n_in,
                              void* d_out, int out_size)
{
    const float* x    = (const float*)d_in[0];
    const float* cosf = (const float*)d_in[1];
    const float* sinf = (const float*)d_in[2];
    const float* wq = (const float*)d_in[7];
    const float* wk = (const float*)d_in[8];
    const float* wv = (const float*)d_in[9];
    const float* wo = (const float*)d_in[10];

    float* out = (float*)d_out;
    float* ck = out + (size_t)MTOT * DD;
    float* cv = ck + (size_t)BB * SWIN * NKVH * HD;

    float *xq, *xk, *xv;
    int8_t *x8h, *x8l, *wq8h, *wq8l, *wk8h, *wk8l, *wv8h, *wv8l;
    __nv_bfloat16 *woh, *wol, *ah, *al;
    cudaGetSymbolAddress((void**)&xq, g_xq);
    cudaGetSymbolAddress((void**)&xk, g_xk);
    cudaGetSymbolAddress((void**)&xv, g_xv);
    cudaGetSymbolAddress((void**)&x8h, g_x8h);
    cudaGetSymbolAddress((void**)&x8l, g_x8l);
    cudaGetSymbolAddress((void**)&wq8h, g_wq8h);
    cudaGetSymbolAddress((void**)&wq8l, g_wq8l);
    cudaGetSymbolAddress((void**)&wk8h, g_wk8h);
    cudaGetSymbolAddress((void**)&wk8l, g_wk8l);
    cudaGetSymbolAddress((void**)&wv8h, g_wv8h);
    cudaGetSymbolAddress((void**)&wv8l, g_wv8l);
    cudaGetSymbolAddress((void**)&woh, g_woh);
    cudaGetSymbolAddress((void**)&wol, g_wol);
    cudaGetSymbolAddress((void**)&ah, g_ah);
    cudaGetSymbolAddress((void**)&al, g_al);

    cudaFuncSetAttribute(igemm3, cudaFuncAttributeMaxDynamicSharedMemorySize, ISMEM);
    cudaFuncSetAttribute(hgemm3, cudaFuncAttributeMaxDynamicSharedMemorySize, GSMEM);
    cudaFuncSetAttribute(flash2_kernel, cudaFuncAttributeMaxDynamicSharedMemorySize, FSMEM);

    // pre-pass: quantize x + qkv weights (int8), transpose+split wo (bf16)
    {
        int n4 = (int)((size_t)MTOT * DD / 4);
        quantx_kernel<<<(n4 + 255) / 256, 256>>>((const float4*)x, x8h, x8l, n4);
        dim3 blk(32, 8);
        qtsplit_kernel<<<dim3(DD / 32, DD / 32), blk>>>(wq, wq8h, wq8l, DD, DD);
        qtsplit_kernel<<<dim3((NKVH * HD) / 32, DD / 32), blk>>>(wk, wk8h, wk8l, DD, NKVH * HD);
        qtsplit_kernel<<<dim3((NKVH * HD) / 32, DD / 32), blk>>>(wv, wv8h, wv8l, DD, NKVH * HD);
        tsplit_kernel<<<dim3(DD / 32, DD / 32), blk>>>(wo, woh, wol, NH * HD, DD);
    }

    // QKV projections (int8 IMMA)
    igemm3<<<dim3(DD / IBN, MTOT / IBM), 256, ISMEM>>>(x8h, x8l, wq8h, wq8l, xq, MTOT, DD, DD);
    igemm3<<<dim3((NKVH * HD) / IBN, MTOT / IBM), 256, ISMEM>>>(x8h, x8l, wk8h, wk8l, xk, MTOT, NKVH * HD, DD);
    igemm3<<<dim3((NKVH * HD) / IBN, MTOT / IBM), 256, ISMEM>>>(x8h, x8l, wv8h, wv8l, xv, MTOT, NKVH * HD, DD);

    // RoPE
    {
        size_t tq = (size_t)BB * SS * NH * (HD / 2);
        rope_kernel<<<(unsigned)((tq + 255) / 256), 256>>>(xq, cosf, sinf, NH);
        size_t tk = (size_t)BB * SS * NKVH * (HD / 2);
        rope_kernel<<<(unsigned)((tk + 255) / 256), 256>>>(xk, cosf, sinf, NKVH);
    }

    // cache outputs
    {
        size_t tc = (size_t)BB * SWIN * NKVH * HD;
        cache_kernel<<<(unsigned)((tc + 255) / 256), 256>>>(xk, xv, ck, cv);
    }

    // attention
    {
        dim3 gf(SS / 32, NH, BB);
        flash2_kernel<<<gf, 128, FSMEM>>>(xq, xk, xv, ah, al);
    }

    // output projection (bf16x3 HMMA)
    hgemm3<<<dim3(DD / GN, MTOT / GM), 256, GSMEM>>>(ah, al, woh, wol, out, MTOT, DD, NH * HD);
}